// round 1
// baseline (speedup 1.0000x reference)
#include <cuda_runtime.h>
#include <cuda_bf16.h>
#include <cstdint>
#include <cstddef>

// Problem dims (fixed)
#define B_   4
#define S_   4096
#define D_   1024
#define QK_  128
#define H_   2048
#define NBROWS (B_ * S_)   // 16384

// ------------------------- device scratch (static, no allocation) -------------
__device__ __nv_bfloat16 g_normed[(size_t)NBROWS * D_];
__device__ __nv_bfloat16 g_Wh [(size_t)D_ * 2 * H_];
__device__ __nv_bfloat16 g_Wqk[(size_t)D_ * QK_];
__device__ __nv_bfloat16 g_Wo [(size_t)H_ * D_];
__device__ __nv_bfloat16 g_v   [(size_t)NBROWS * H_];
__device__ __nv_bfloat16 g_gate[(size_t)NBROWS * H_];
__device__ __nv_bfloat16 g_q   [(size_t)NBROWS * QK_];
__device__ __nv_bfloat16 g_kT  [(size_t)B_ * QK_ * S_];
__device__ __nv_bfloat16 g_attn[(size_t)B_ * S_ * S_];
__device__ __nv_bfloat16 g_og  [(size_t)NBROWS * H_];
__device__ float g_bias_lut[2 * S_ - 1];

// ------------------------- prep: weight conversion + rel-bias LUT -------------
__global__ void prep_kernel(const float* __restrict__ Wh,
                            const float* __restrict__ Wqk,
                            const float* __restrict__ Wo,
                            const float* __restrict__ rel_emb)
{
    int i = blockIdx.x * blockDim.x + threadIdx.x;
    const int nWh  = D_ * 2 * H_;   // 4194304
    const int nWqk = D_ * QK_;      // 131072
    const int nWo  = H_ * D_;       // 2097152
    if (i < nWh) { g_Wh[i] = __float2bfloat16(Wh[i]); return; }
    i -= nWh;
    if (i < nWqk) { g_Wqk[i] = __float2bfloat16(Wqk[i]); return; }
    i -= nWqk;
    if (i < nWo) { g_Wo[i] = __float2bfloat16(Wo[i]); return; }
    i -= nWo;
    if (i < 2 * S_ - 1) {
        // lut index li covers d = j - i in [-(S-1), S-1]; n = -d
        int d = i - (S_ - 1);
        int n = -d;
        int ret = (n < 0) ? 16 : 0;
        int na = n < 0 ? -n : n;
        int b;
        if (na < 8) {
            b = na;
        } else {
            float v = logf((float)na / 8.0f) / logf(16.0f) * 8.0f;
            int vi = 8 + (int)v;       // truncation toward zero (v >= 0 here)
            b = vi < 15 ? vi : 15;
        }
        int bucket = ret + b;
        g_bias_lut[i] = rel_emb[bucket] * 32.0f;  // scale = sqrt(D) = 32
    }
}

// ------------------------- LayerNorm: x -> normed (bf16) ----------------------
__global__ void ln_kernel(const float* __restrict__ x,
                          const float* __restrict__ gamma,
                          const float* __restrict__ beta)
{
    int row = blockIdx.x;
    const float4* xr = reinterpret_cast<const float4*>(x + (size_t)row * D_);
    float4 v = xr[threadIdx.x];                 // 256 threads * 4 = 1024
    float s  = v.x + v.y + v.z + v.w;
    float ss = fmaf(v.x, v.x, fmaf(v.y, v.y, fmaf(v.z, v.z, v.w * v.w)));
    #pragma unroll
    for (int o = 16; o; o >>= 1) {
        s  += __shfl_xor_sync(0xFFFFFFFFu, s,  o);
        ss += __shfl_xor_sync(0xFFFFFFFFu, ss, o);
    }
    __shared__ float sh[2][8];
    int lane = threadIdx.x & 31, w = threadIdx.x >> 5;
    if (lane == 0) { sh[0][w] = s; sh[1][w] = ss; }
    __syncthreads();
    if (threadIdx.x < 32) {
        float a = (threadIdx.x < 8) ? sh[0][threadIdx.x] : 0.f;
        float b = (threadIdx.x < 8) ? sh[1][threadIdx.x] : 0.f;
        #pragma unroll
        for (int o = 4; o; o >>= 1) {
            a += __shfl_xor_sync(0xFFFFFFFFu, a, o);
            b += __shfl_xor_sync(0xFFFFFFFFu, b, o);
        }
        if (threadIdx.x == 0) { sh[0][0] = a; sh[1][0] = b; }
    }
    __syncthreads();
    float mean = sh[0][0] * (1.0f / D_);
    float var  = sh[1][0] * (1.0f / D_) - mean * mean;
    float r = rsqrtf(var + 1e-5f);
    int c = threadIdx.x * 4;
    __nv_bfloat16* o = g_normed + (size_t)row * D_;
    o[c + 0] = __float2bfloat16((v.x - mean) * r * gamma[c + 0] + beta[c + 0]);
    o[c + 1] = __float2bfloat16((v.y - mean) * r * gamma[c + 1] + beta[c + 1]);
    o[c + 2] = __float2bfloat16((v.z - mean) * r * gamma[c + 2] + beta[c + 2]);
    o[c + 3] = __float2bfloat16((v.w - mean) * r * gamma[c + 3] + beta[c + 3]);
}

// ------------------------- generic bf16 tensor-core GEMM ----------------------
#define BM 128
#define BN 128
#define BK 32
#define LDA_S 40    // elements (80 bytes) -> conflict-free ldmatrix
#define LDB_S 136   // elements (272 bytes)

__device__ __forceinline__ uint32_t s2u(const void* p) {
    return (uint32_t)__cvta_generic_to_shared(p);
}

#define CP16(dst, src) \
    asm volatile("cp.async.cg.shared.global [%0], [%1], 16;\n" :: "r"(dst), "l"(src))

// EPI: 0=hidden(silu->v/gate)  1=qk(silu->q,kT)  2=sim(bias,relu^2->attn)
//      3=av(*gate->og)         4=out(+bo+x->d_out)
template<int EPI, int Mc, int Nc, int Kc>
__global__ void __launch_bounds__(256)
gemm_kernel(const float* __restrict__ p0, const float* __restrict__ p1,
            const float* __restrict__ p2, float* __restrict__ pout)
{
    __shared__ __nv_bfloat16 As[2][BM][LDA_S];
    __shared__ __nv_bfloat16 Bs[2][BK][LDB_S];

    const __nv_bfloat16* A;
    const __nv_bfloat16* Bg;
    if constexpr (EPI == 0)      { A = g_normed; Bg = g_Wh; }
    else if constexpr (EPI == 1) { A = g_normed; Bg = g_Wqk; }
    else if constexpr (EPI == 2) { A = g_q   + (size_t)blockIdx.z * S_ * QK_;
                                   Bg = g_kT + (size_t)blockIdx.z * QK_ * S_; }
    else if constexpr (EPI == 3) { A = g_attn + (size_t)blockIdx.z * S_ * S_;
                                   Bg = g_v   + (size_t)blockIdx.z * S_ * H_; }
    else                         { A = g_og; Bg = g_Wo; }

    const int tid  = threadIdx.x;
    const int lane = tid & 31;
    const int warp = tid >> 5;
    const int warp_m = (warp >> 1) * 32;
    const int warp_n = (warp & 1) * 64;
    const int bm = blockIdx.y * BM;
    const int bn = blockIdx.x * BN;

    // gmem -> smem tiling (16B chunks, 2 per thread per operand)
    const int arow = tid >> 2;            // 0..63
    const int acol = (tid & 3) * 8;       // element offset in K
    const int brow = tid >> 4;            // 0..15
    const int bcol = (tid & 15) * 8;      // element offset in N

    const __nv_bfloat16* a_src0 = A + (size_t)(bm + arow) * Kc + acol;
    const __nv_bfloat16* a_src1 = a_src0 + (size_t)64 * Kc;
    const __nv_bfloat16* b_src0 = Bg + (size_t)brow * Nc + bn + bcol;
    const __nv_bfloat16* b_src1 = b_src0 + (size_t)16 * Nc;

    const uint32_t a_dst0 = s2u(&As[0][arow][acol]);
    const uint32_t a_dst1 = s2u(&As[0][64 + arow][acol]);
    const uint32_t b_dst0 = s2u(&Bs[0][brow][bcol]);
    const uint32_t b_dst1 = s2u(&Bs[0][16 + brow][bcol]);
    const uint32_t Asz = BM * LDA_S * 2;  // bytes per A buffer
    const uint32_t Bsz = BK * LDB_S * 2;

    // ldmatrix per-lane offsets (same formula works for A and trans-B)
    const int q8    = lane >> 3;
    const int lrow  = (lane & 7) + (q8 & 1) * 8;
    const int lcol8 = (q8 >> 1) * 8;
    const uint32_t a_lm_base = s2u(&As[0][warp_m + lrow][lcol8]);
    const uint32_t b_lm_base = s2u(&Bs[0][lrow][warp_n + lcol8]);

    // prologue: tile 0
    CP16(a_dst0, a_src0); CP16(a_dst1, a_src1);
    CP16(b_dst0, b_src0); CP16(b_dst1, b_src1);
    asm volatile("cp.async.commit_group;\n");

    float c[2][8][4] = {};
    const int KT = Kc / BK;

    for (int kt = 0; kt < KT; ++kt) {
        asm volatile("cp.async.wait_group 0;\n");
        __syncthreads();
        const int buf = kt & 1;
        if (kt + 1 < KT) {
            const uint32_t offA = ((kt + 1) & 1) ? Asz : 0;
            const uint32_t offB = ((kt + 1) & 1) ? Bsz : 0;
            const __nv_bfloat16* a0 = a_src0 + (size_t)(kt + 1) * BK;
            const __nv_bfloat16* a1 = a_src1 + (size_t)(kt + 1) * BK;
            const __nv_bfloat16* b0 = b_src0 + (size_t)(kt + 1) * BK * Nc;
            const __nv_bfloat16* b1 = b_src1 + (size_t)(kt + 1) * BK * Nc;
            CP16(a_dst0 + offA, a0); CP16(a_dst1 + offA, a1);
            CP16(b_dst0 + offB, b0); CP16(b_dst1 + offB, b1);
            asm volatile("cp.async.commit_group;\n");
        }
        #pragma unroll
        for (int s = 0; s < 2; ++s) {
            uint32_t a[2][4];
            #pragma unroll
            for (int mf = 0; mf < 2; ++mf) {
                uint32_t addr = a_lm_base + buf * Asz + mf * (16 * LDA_S * 2) + s * 32;
                asm volatile("ldmatrix.sync.aligned.m8n8.x4.shared.b16 {%0,%1,%2,%3},[%4];"
                    : "=r"(a[mf][0]), "=r"(a[mf][1]), "=r"(a[mf][2]), "=r"(a[mf][3])
                    : "r"(addr));
            }
            uint32_t bf[8][2];
            #pragma unroll
            for (int nq = 0; nq < 4; ++nq) {
                uint32_t addr = b_lm_base + buf * Bsz + s * (16 * LDB_S * 2) + nq * 32;
                uint32_t r0, r1, r2, r3;
                asm volatile("ldmatrix.sync.aligned.m8n8.x4.trans.shared.b16 {%0,%1,%2,%3},[%4];"
                    : "=r"(r0), "=r"(r1), "=r"(r2), "=r"(r3) : "r"(addr));
                bf[nq * 2][0] = r0; bf[nq * 2][1] = r1;
                bf[nq * 2 + 1][0] = r2; bf[nq * 2 + 1][1] = r3;
            }
            #pragma unroll
            for (int mf = 0; mf < 2; ++mf)
                #pragma unroll
                for (int nf = 0; nf < 8; ++nf)
                    asm volatile(
                        "mma.sync.aligned.m16n8k16.row.col.f32.bf16.bf16.f32 "
                        "{%0,%1,%2,%3},{%4,%5,%6,%7},{%8,%9},{%0,%1,%2,%3};"
                        : "+f"(c[mf][nf][0]), "+f"(c[mf][nf][1]),
                          "+f"(c[mf][nf][2]), "+f"(c[mf][nf][3])
                        : "r"(a[mf][0]), "r"(a[mf][1]), "r"(a[mf][2]), "r"(a[mf][3]),
                          "r"(bf[nf][0]), "r"(bf[nf][1]));
        }
    }

    // epilogue
    const int gr = bm + warp_m + (lane >> 2);
    const int gc = bn + warp_n + (lane & 3) * 2;
    #pragma unroll
    for (int mf = 0; mf < 2; ++mf)
    #pragma unroll
    for (int nf = 0; nf < 8; ++nf)
    #pragma unroll
    for (int e = 0; e < 4; ++e) {
        const int row = gr + mf * 16 + ((e >> 1) << 3);
        const int col = gc + nf * 8 + (e & 1);
        const float acc = c[mf][nf][e];
        if constexpr (EPI == 0) {
            float z = acc + p0[col];
            float sv = z / (1.0f + expf(-z));
            if (col < H_) g_v[(size_t)row * H_ + col] = __float2bfloat16(sv);
            else          g_gate[(size_t)row * H_ + (col - H_)] = __float2bfloat16(sv);
        } else if constexpr (EPI == 1) {
            float z = acc + p0[col];
            float sv = z / (1.0f + expf(-z));
            float qv = sv * p1[col]       + p2[col];
            float kv = sv * p1[QK_ + col] + p2[QK_ + col];
            g_q[(size_t)row * QK_ + col] = __float2bfloat16(qv);
            int bb = row >> 12;          // row / 4096
            int ii = row & (S_ - 1);
            g_kT[((size_t)bb * QK_ + col) * S_ + ii] = __float2bfloat16(kv);
        } else if constexpr (EPI == 2) {
            float bias = g_bias_lut[col - row + (S_ - 1)];
            float t = (acc + bias) * (1.0f / (float)S_);
            t = fmaxf(t, 0.0f);
            g_attn[((size_t)blockIdx.z * S_ + row) * S_ + col] = __float2bfloat16(t * t);
        } else if constexpr (EPI == 3) {
            size_t mg = (size_t)blockIdx.z * S_ + row;
            float gv = __bfloat162float(g_gate[mg * H_ + col]);
            g_og[mg * H_ + col] = __float2bfloat16(acc * gv);
        } else {
            size_t idx = (size_t)row * D_ + col;
            pout[idx] = acc + p0[col] + p1[idx];
        }
    }
}

// ------------------------------- launch ---------------------------------------
extern "C" void kernel_launch(void* const* d_in, const int* in_sizes, int n_in,
                              void* d_out, int out_size)
{
    const float* x    = (const float*)d_in[0];
    const float* ln_g = (const float*)d_in[1];
    const float* ln_b = (const float*)d_in[2];
    const float* Wh   = (const float*)d_in[3];
    const float* bh   = (const float*)d_in[4];
    const float* Wqk  = (const float*)d_in[5];
    const float* bqk  = (const float*)d_in[6];
    const float* osg  = (const float*)d_in[7];
    const float* osb  = (const float*)d_in[8];
    const float* Wo   = (const float*)d_in[9];
    const float* bo   = (const float*)d_in[10];
    const float* rel  = (const float*)d_in[11];
    float* out = (float*)d_out;

    const int prep_total = D_ * 2 * H_ + D_ * QK_ + H_ * D_ + (2 * S_ - 1);
    prep_kernel<<<(prep_total + 255) / 256, 256>>>(Wh, Wqk, Wo, rel);
    ln_kernel<<<NBROWS, 256>>>(x, ln_g, ln_b);

    // hidden = silu(normed @ Wh + bh) -> v, gate
    gemm_kernel<0, NBROWS, 2 * H_, D_>
        <<<dim3((2 * H_) / BN, NBROWS / BM, 1), 256>>>(bh, nullptr, nullptr, nullptr);
    // qk = silu(normed @ Wqk + bqk) -> q, kT
    gemm_kernel<1, NBROWS, QK_, D_>
        <<<dim3(QK_ / BN, NBROWS / BM, 1), 256>>>(bqk, osg, osb, nullptr);
    // attn = relu((q kT + bias)/S)^2   (per batch)
    gemm_kernel<2, S_, S_, QK_>
        <<<dim3(S_ / BN, S_ / BM, B_), 256>>>(nullptr, nullptr, nullptr, nullptr);
    // og = (attn @ v) * gate           (per batch)
    gemm_kernel<3, S_, H_, S_>
        <<<dim3(H_ / BN, S_ / BM, B_), 256>>>(nullptr, nullptr, nullptr, nullptr);
    // out = og @ Wo + bo + x
    gemm_kernel<4, NBROWS, D_, H_>
        <<<dim3(D_ / BN, NBROWS / BM, 1), 256>>>(bo, x, nullptr, out);
}